// round 6
// baseline (speedup 1.0000x reference)
#include <cuda_runtime.h>

#define T_TRIG 48
#define S_SPAN 128
#define NNODE  (T_TRIG * S_SPAN)     // 6144
#define DIM    128
#define NHEADS 4
#define HDIM   32

typedef unsigned long long ull;

__device__ float g_h   [NNODE * DIM];
__device__ float g_A   [NNODE * NHEADS];
__device__ float g_B   [NNODE * NHEADS];
__device__ float g_EA  [NNODE * NHEADS];
__device__ float g_EA5 [NNODE * NHEADS];
__device__ float g_EB  [NNODE * NHEADS];
__device__ float g_EB5 [NNODE * NHEADS];
__device__ float g_srow[NNODE * NHEADS];
__device__ float g_tmp [NNODE * DIM];
__device__ float g_x1  [NNODE * DIM];

// ---- packed f32x2 helpers -------------------------------------------------
__device__ __forceinline__ ull pk2(float x, float y) {
    ull r; asm("mov.b64 %0, {%1, %2};" : "=l"(r) : "f"(x), "f"(y)); return r;
}
__device__ __forceinline__ float2 upk2(ull v) {
    float2 r; asm("mov.b64 {%0, %1}, %2;" : "=f"(r.x), "=f"(r.y) : "l"(v)); return r;
}
__device__ __forceinline__ void fma2(ull& d, ull a, ull b) {
    asm("fma.rn.f32x2 %0, %1, %2, %0;" : "+l"(d) : "l"(a), "l"(b));
}

// ---------------------------------------------------------------------------
// K1: h = x @ W + attention dots + 4 exps per (node,head).
// Tile M=16, N=128; 256 threads; thread = 2 rows x 4 cols (2 f32x2 col-pairs).
// grid = 384. b-operand = natural ulonglong2 from k-major W.
// ---------------------------------------------------------------------------
__global__ void __launch_bounds__(256)
k_gemm_attn(const float* __restrict__ x,
            const float* __restrict__ W,
            const float* __restrict__ att_src,
            const float* __restrict__ att_dst)
{
    __shared__ __align__(16) float xs[16 * 128];
    const int tid  = threadIdx.x;
    const int row0 = blockIdx.x * 16;

    ((float4*)xs)[tid]       = ((const float4*)(x + row0 * 128))[tid];
    ((float4*)xs)[tid + 256] = ((const float4*)(x + row0 * 128))[tid + 256];
    __syncthreads();

    const int ng = tid & 31;   // col group: cols ng*4..+3
    const int mg = tid >> 5;   // row group: rows mg*2..+1

    ull acc2[2][2];
    acc2[0][0] = acc2[0][1] = acc2[1][0] = acc2[1][1] = 0ull;

#pragma unroll 4
    for (int k4 = 0; k4 < 32; k4++) {
        ulonglong2 wv[4];
#pragma unroll
        for (int kk = 0; kk < 4; kk++)
            wv[kk] = *(const ulonglong2*)&W[(k4 * 4 + kk) * 128 + ng * 4];
#pragma unroll
        for (int r = 0; r < 2; r++) {
            const float4 xv = *(const float4*)&xs[(mg * 2 + r) * 128 + k4 * 4];
            ull xx;
            xx = pk2(xv.x, xv.x); fma2(acc2[r][0], xx, wv[0].x); fma2(acc2[r][1], xx, wv[0].y);
            xx = pk2(xv.y, xv.y); fma2(acc2[r][0], xx, wv[1].x); fma2(acc2[r][1], xx, wv[1].y);
            xx = pk2(xv.z, xv.z); fma2(acc2[r][0], xx, wv[2].x); fma2(acc2[r][1], xx, wv[2].y);
            xx = pk2(xv.w, xv.w); fma2(acc2[r][0], xx, wv[3].x); fma2(acc2[r][1], xx, wv[3].y);
        }
    }

    float acc[2][4];
#pragma unroll
    for (int r = 0; r < 2; r++) {
        const float2 lo = upk2(acc2[r][0]);
        const float2 hi = upk2(acc2[r][1]);
        acc[r][0] = lo.x; acc[r][1] = lo.y; acc[r][2] = hi.x; acc[r][3] = hi.y;
        *(float4*)&g_h[(row0 + mg * 2 + r) * 128 + ng * 4] =
            make_float4(lo.x, lo.y, hi.x, hi.y);
    }

    const int head = ng >> 3;
    const float4 asv = *(const float4*)&att_src[head * 32 + (ng & 7) * 4];
    const float4 adv = *(const float4*)&att_dst[head * 32 + (ng & 7) * 4];

#pragma unroll
    for (int r = 0; r < 2; r++) {
        float ps = acc[r][0] * asv.x + acc[r][1] * asv.y + acc[r][2] * asv.z + acc[r][3] * asv.w;
        float pd = acc[r][0] * adv.x + acc[r][1] * adv.y + acc[r][2] * adv.z + acc[r][3] * adv.w;
#pragma unroll
        for (int o = 1; o < 8; o <<= 1) {
            ps += __shfl_xor_sync(0xffffffffu, ps, o);
            pd += __shfl_xor_sync(0xffffffffu, pd, o);
        }
        if ((ng & 7) == 0) {
            const int n = row0 + mg * 2 + r;
            const int i4 = n * 4 + head;
            g_A  [i4] = ps;
            g_B  [i4] = pd;
            g_EA [i4] = __expf(ps);
            g_EA5[i4] = __expf(0.2f * ps);
            g_EB [i4] = __expf(pd);
            g_EB5[i4] = __expf(0.2f * pd);
        }
    }
}

// ---------------------------------------------------------------------------
// K2: row aggregation (unnormalized) + row part of softmax denominator.
// Block = (r, head, c-half). grid = 384, 128 threads, f32x2 inner loop.
// ---------------------------------------------------------------------------
__global__ void __launch_bounds__(128)
k_row_agg()
{
    const int b  = blockIdx.x;
    const int r  = b >> 3;
    const int hh = (b >> 1) & 3;
    const int ch = b & 1;

    __shared__ __align__(16) float Hs[128 * 36];
    __shared__ __align__(16) float ws[32 * 68];
    __shared__ float As[128], EAs[128], EA5s[128];
    __shared__ float Bs[64], EBs[64], EB5s[64];
    __shared__ float Ssum2[2][64];

    const int tid = threadIdx.x;

#pragma unroll
    for (int i = tid; i < 1024; i += 128) {
        const int cp = i >> 3, v = i & 7;
        *(float4*)&Hs[cp * 36 + v * 4] =
            *(const float4*)&g_h[(r * 128 + cp) * 128 + hh * 32 + v * 4];
    }
    {
        const int idx = (r * 128 + tid) * 4 + hh;
        As  [tid] = g_A  [idx];
        EAs [tid] = g_EA [idx];
        EA5s[tid] = g_EA5[idx];
    }
    if (tid < 64) {
        const int idx = (r * 128 + ch * 64 + tid) * 4 + hh;
        Bs  [tid] = g_B  [idx];
        EBs [tid] = g_EB [idx];
        EB5s[tid] = g_EB5[idx];
    }
    __syncthreads();

    const int d  = tid & 63;
    const int jh = tid >> 6;
    const float Bv   = Bs[d];
    const float EBv  = EBs[d];
    const float EB5v = EB5s[d];
    float srun = 0.f;

    const int dg = tid >> 3;
    const int qg = tid & 7;

    ull acc2[4][2];
#pragma unroll
    for (int a = 0; a < 4; a++) { acc2[a][0] = 0ull; acc2[a][1] = 0ull; }

    for (int cc = 0; cc < 4; cc++) {
#pragma unroll
        for (int jj = 0; jj < 16; jj++) {
            const int j  = jh * 16 + jj;
            const int jx = cc * 32 + j;
            const float xv = As[jx] + Bv;
            const float w = xv > 0.f ? EAs[jx] * EBv : EA5s[jx] * EB5v;
            ws[j * 68 + d] = w;
            srun += w;
        }
        __syncthreads();

#pragma unroll
        for (int j = 0; j < 32; j++) {
            const float4 wv = *(const float4*)&ws[j * 68 + dg * 4];
            const ulonglong2 hv = *(const ulonglong2*)&Hs[(cc * 32 + j) * 36 + qg * 4];
            ull ww;
            ww = pk2(wv.x, wv.x); fma2(acc2[0][0], ww, hv.x); fma2(acc2[0][1], ww, hv.y);
            ww = pk2(wv.y, wv.y); fma2(acc2[1][0], ww, hv.x); fma2(acc2[1][1], ww, hv.y);
            ww = pk2(wv.z, wv.z); fma2(acc2[2][0], ww, hv.x); fma2(acc2[2][1], ww, hv.y);
            ww = pk2(wv.w, wv.w); fma2(acc2[3][0], ww, hv.x); fma2(acc2[3][1], ww, hv.y);
        }
        __syncthreads();
    }

#pragma unroll
    for (int a = 0; a < 4; a++) {
        const int dst = ch * 64 + dg * 4 + a;
        const float2 lo = upk2(acc2[a][0]);
        const float2 hi = upk2(acc2[a][1]);
        *(float4*)&g_tmp[(r * 128 + dst) * 128 + hh * 32 + qg * 4] =
            make_float4(lo.x, lo.y, hi.x, hi.y);
    }

    Ssum2[jh][d] = srun;
    __syncthreads();
    if (tid < 64)
        g_srow[(r * 128 + ch * 64 + tid) * 4 + hh] = Ssum2[0][tid] + Ssum2[1][tid];
}

// ---------------------------------------------------------------------------
// K3: column aggregation + denominator finalize + normalize + bias + ELU.
// Block per column c: grid = 128, 384 threads, f32x2 inner loop.
// ---------------------------------------------------------------------------
__global__ void __launch_bounds__(384)
k_col_agg(const float* __restrict__ bias, float* __restrict__ out)
{
    const int c   = blockIdx.x;
    const int tid = threadIdx.x;

    __shared__ __align__(16) float Hs[48 * 136];
    __shared__ __align__(16) float ws[16 * 224];
    __shared__ float Acol[192], EAc[192], EA5c[192];
    __shared__ float Brc[192], EBrc[192], EB5rc[192];
    __shared__ float Srow[192], Rd[192];
    __shared__ float Sc2[2][192];
    __shared__ float bsh[128];

#pragma unroll
    for (int i = tid; i < 1536; i += 384) {
        const int t = i >> 5, v = i & 31;
        *(float4*)&Hs[t * 136 + v * 4] =
            *(const float4*)&g_h[(t * 128 + c) * 128 + v * 4];
    }
    if (tid < 192) {
        const int t = tid >> 2, h = tid & 3;
        const int idx = (t * 128 + c) * 4 + h;
        Acol [tid] = g_A   [idx];
        EAc  [tid] = g_EA  [idx];
        EA5c [tid] = g_EA5 [idx];
        Brc  [tid] = g_B   [idx];
        EBrc [tid] = g_EB  [idx];
        EB5rc[tid] = g_EB5 [idx];
        Srow [tid] = g_srow[idx];
    } else if (tid < 320) {
        bsh[tid - 192] = bias[tid - 192];
    }
    __syncthreads();

    const int k    = tid < 192 ? tid : tid - 192;
    const int half = tid < 192 ? 0 : 1;
    const int rr   = k >> 2;
    const int h    = k & 3;
    const float Bv   = Brc[k];
    const float EBv  = EBrc[k];
    const float EB5v = EB5rc[k];
    float scrun = 0.f;

    const int rg   = tid >> 5;
    const int head = (tid >> 3) & 3;
    const int qg   = tid & 7;

    ull acc2[4][2];
#pragma unroll
    for (int a = 0; a < 4; a++) { acc2[a][0] = 0ull; acc2[a][1] = 0ull; }

    for (int chunk = 0; chunk < 3; chunk++) {
        const int t0 = chunk * 16;
#pragma unroll
        for (int i = 0; i < 8; i++) {
            const int tl = half * 8 + i;
            const int t  = t0 + tl;
            const int sx = t * 4 + h;
            const float xv = Acol[sx] + Bv;
            float w = xv > 0.f ? EAc[sx] * EBv : EA5c[sx] * EB5v;
            if (t == rr) w = 0.f;
            ws[tl * 224 + h * 56 + rr] = w;
            scrun += w;
        }
        __syncthreads();

#pragma unroll
        for (int tl = 0; tl < 16; tl++) {
            const float4 wv = *(const float4*)&ws[tl * 224 + head * 56 + rg * 4];
            const ulonglong2 hv =
                *(const ulonglong2*)&Hs[(t0 + tl) * 136 + head * 32 + qg * 4];
            ull ww;
            ww = pk2(wv.x, wv.x); fma2(acc2[0][0], ww, hv.x); fma2(acc2[0][1], ww, hv.y);
            ww = pk2(wv.y, wv.y); fma2(acc2[1][0], ww, hv.x); fma2(acc2[1][1], ww, hv.y);
            ww = pk2(wv.z, wv.z); fma2(acc2[2][0], ww, hv.x); fma2(acc2[2][1], ww, hv.y);
            ww = pk2(wv.w, wv.w); fma2(acc2[3][0], ww, hv.x); fma2(acc2[3][1], ww, hv.y);
        }
        __syncthreads();
    }

    Sc2[half][k] = scrun;
    __syncthreads();
    if (tid < 192)
        Rd[tid] = 1.f / (Srow[tid] + Sc2[0][tid] + Sc2[1][tid]);
    __syncthreads();

    const int bb = head * 32 + qg * 4;
    const float4 bv = *(const float4*)&bsh[bb];
#pragma unroll
    for (int a = 0; a < 4; a++) {
        const int r = rg * 4 + a;
        const float rd = Rd[r * 4 + head];
        const int base = (r * 128 + c) * 128 + bb;
        const float4 tv = *(const float4*)&g_tmp[base];
        const float2 lo = upk2(acc2[a][0]);
        const float2 hi = upk2(acc2[a][1]);
        float v0 = (lo.x + tv.x) * rd + bv.x;
        float v1 = (lo.y + tv.y) * rd + bv.y;
        float v2 = (hi.x + tv.z) * rd + bv.z;
        float v3 = (hi.y + tv.w) * rd + bv.w;
        v0 = v0 > 0.f ? v0 : (__expf(v0) - 1.f);
        v1 = v1 > 0.f ? v1 : (__expf(v1) - 1.f);
        v2 = v2 > 0.f ? v2 : (__expf(v2) - 1.f);
        v3 = v3 > 0.f ? v3 : (__expf(v3) - 1.f);
        *(float4*)&out[base] = make_float4(v0, v1, v2, v3);
    }
}

// ---------------------------------------------------------------------------
static void run_layer(const float* x, const float* W, const float* asrc,
                      const float* adst, const float* bias, float* out)
{
    k_gemm_attn<<<NNODE / 16, 256>>>(x, W, asrc, adst);
    k_row_agg<<<T_TRIG * NHEADS * 2, 128>>>();
    k_col_agg<<<S_SPAN, 384>>>(bias, out);
}

extern "C" void kernel_launch(void* const* d_in, const int* in_sizes, int n_in,
                              void* d_out, int out_size)
{
    const float* x0  = (const float*)d_in[0];
    const float* W1  = (const float*)d_in[1];
    const float* as1 = (const float*)d_in[2];
    const float* ad1 = (const float*)d_in[3];
    const float* b1  = (const float*)d_in[4];
    const float* W2  = (const float*)d_in[5];
    const float* as2 = (const float*)d_in[6];
    const float* ad2 = (const float*)d_in[7];
    const float* b2  = (const float*)d_in[8];

    float* x1 = nullptr;
    cudaGetSymbolAddress((void**)&x1, g_x1);

    run_layer(x0, W1, as1, ad1, b1, x1);
    run_layer(x1, W2, as2, ad2, b2, (float*)d_out);
}

// round 7
// speedup vs baseline: 1.1034x; 1.1034x over previous
#include <cuda_runtime.h>

#define T_TRIG 48
#define S_SPAN 128
#define NNODE  (T_TRIG * S_SPAN)     // 6144
#define DIM    128
#define NHEADS 4
#define HDIM   32

typedef unsigned long long ull;

__device__ float g_h   [NNODE * DIM];
__device__ float g_A   [NNODE * NHEADS];
__device__ float g_B   [NNODE * NHEADS];
__device__ float g_EA  [NNODE * NHEADS];
__device__ float g_EA5 [NNODE * NHEADS];
__device__ float g_EB  [NNODE * NHEADS];
__device__ float g_EB5 [NNODE * NHEADS];
__device__ float g_srow[NNODE * NHEADS];
__device__ float g_tmp [NNODE * DIM];
__device__ float g_x1  [NNODE * DIM];

// ---- packed f32x2 helpers -------------------------------------------------
__device__ __forceinline__ ull pk2(float x, float y) {
    ull r; asm("mov.b64 %0, {%1, %2};" : "=l"(r) : "f"(x), "f"(y)); return r;
}
__device__ __forceinline__ float2 upk2(ull v) {
    float2 r; asm("mov.b64 {%0, %1}, %2;" : "=f"(r.x), "=f"(r.y) : "l"(v)); return r;
}
__device__ __forceinline__ void fma2(ull& d, ull a, ull b) {
    asm("fma.rn.f32x2 %0, %1, %2, %0;" : "+l"(d) : "l"(a), "l"(b));
}

// ---------------------------------------------------------------------------
// K1: h = x @ W + attention dots + 4 exps per (node,head).
// Block = 128 threads (4 warps), M=16, N=128, grid = 384 (fully resident).
// Warp w = head w = cols w*32..+31; lane = (mg=lane>>3 -> 4 rows, ng=lane&7
// -> 4 cols). Thread tile 4x4. W streamed via smem in 4 chunks of 32 k-rows,
// register-prefetched; inner loop has NO global loads.
// ---------------------------------------------------------------------------
__global__ void __launch_bounds__(128)
k_gemm_attn(const float* __restrict__ x,
            const float* __restrict__ W,
            const float* __restrict__ att_src,
            const float* __restrict__ att_dst)
{
    __shared__ __align__(16) float xs[16 * 128];   // 8 KB
    __shared__ __align__(16) float Wb[32 * 128];   // 16 KB (one k-chunk)

    const int tid  = threadIdx.x;
    const int row0 = blockIdx.x * 16;

    // prologue: stage x block (512 float4) and W chunk 0 (1024 float4)
#pragma unroll
    for (int i = 0; i < 4; i++)
        ((float4*)xs)[tid + 128 * i] = ((const float4*)(x + row0 * 128))[tid + 128 * i];
#pragma unroll
    for (int i = 0; i < 8; i++)
        ((float4*)Wb)[tid + 128 * i] = ((const float4*)W)[tid + 128 * i];
    __syncthreads();

    const int warp = tid >> 5;
    const int lane = tid & 31;
    const int mg   = lane >> 3;       // row group (4 rows)
    const int ng   = lane & 7;        // col group (4 cols)
    const int wcol = warp * 32 + ng * 4;

    ull acc2[4][2];
#pragma unroll
    for (int r = 0; r < 4; r++) { acc2[r][0] = 0ull; acc2[r][1] = 0ull; }

    for (int cc = 0; cc < 4; cc++) {
        // prefetch next W chunk into registers
        float4 pre[8];
        if (cc < 3) {
#pragma unroll
            for (int i = 0; i < 8; i++)
                pre[i] = ((const float4*)W)[(cc + 1) * 1024 + tid + 128 * i];
        }

#pragma unroll
        for (int k4 = 0; k4 < 8; k4++) {
            ulonglong2 wv[4];
#pragma unroll
            for (int kk = 0; kk < 4; kk++)
                wv[kk] = *(const ulonglong2*)&Wb[(k4 * 4 + kk) * 128 + wcol];
#pragma unroll
            for (int r = 0; r < 4; r++) {
                const float4 xv = *(const float4*)&xs[(mg * 4 + r) * 128 + (cc * 8 + k4) * 4];
                ull xx;
                xx = pk2(xv.x, xv.x); fma2(acc2[r][0], xx, wv[0].x); fma2(acc2[r][1], xx, wv[0].y);
                xx = pk2(xv.y, xv.y); fma2(acc2[r][0], xx, wv[1].x); fma2(acc2[r][1], xx, wv[1].y);
                xx = pk2(xv.z, xv.z); fma2(acc2[r][0], xx, wv[2].x); fma2(acc2[r][1], xx, wv[2].y);
                xx = pk2(xv.w, xv.w); fma2(acc2[r][0], xx, wv[3].x); fma2(acc2[r][1], xx, wv[3].y);
            }
        }

        if (cc < 3) {
            __syncthreads();   // everyone done reading Wb for this chunk
#pragma unroll
            for (int i = 0; i < 8; i++)
                ((float4*)Wb)[tid + 128 * i] = pre[i];
            __syncthreads();   // new chunk visible
        }
    }

    // store h + attention dot products (head == warp)
    float acc[4][4];
#pragma unroll
    for (int r = 0; r < 4; r++) {
        const float2 lo = upk2(acc2[r][0]);
        const float2 hi = upk2(acc2[r][1]);
        acc[r][0] = lo.x; acc[r][1] = lo.y; acc[r][2] = hi.x; acc[r][3] = hi.y;
        *(float4*)&g_h[(row0 + mg * 4 + r) * 128 + wcol] =
            make_float4(lo.x, lo.y, hi.x, hi.y);
    }

    const float4 asv = *(const float4*)&att_src[warp * 32 + ng * 4];
    const float4 adv = *(const float4*)&att_dst[warp * 32 + ng * 4];

#pragma unroll
    for (int r = 0; r < 4; r++) {
        float ps = acc[r][0] * asv.x + acc[r][1] * asv.y + acc[r][2] * asv.z + acc[r][3] * asv.w;
        float pd = acc[r][0] * adv.x + acc[r][1] * adv.y + acc[r][2] * adv.z + acc[r][3] * adv.w;
#pragma unroll
        for (int o = 1; o < 8; o <<= 1) {
            ps += __shfl_xor_sync(0xffffffffu, ps, o);
            pd += __shfl_xor_sync(0xffffffffu, pd, o);
        }
        if (ng == 0) {
            const int n  = row0 + mg * 4 + r;
            const int i4 = n * 4 + warp;
            g_A  [i4] = ps;
            g_B  [i4] = pd;
            g_EA [i4] = __expf(ps);
            g_EA5[i4] = __expf(0.2f * ps);
            g_EB [i4] = __expf(pd);
            g_EB5[i4] = __expf(0.2f * pd);
        }
    }
}

// ---------------------------------------------------------------------------
// K2: row aggregation (unnormalized) + row part of softmax denominator.
// Block = (r, head, c-half). grid = 384, 128 threads, f32x2 inner loop.
// ---------------------------------------------------------------------------
__global__ void __launch_bounds__(128)
k_row_agg()
{
    const int b  = blockIdx.x;
    const int r  = b >> 3;
    const int hh = (b >> 1) & 3;
    const int ch = b & 1;

    __shared__ __align__(16) float Hs[128 * 36];
    __shared__ __align__(16) float ws[32 * 68];
    __shared__ float As[128], EAs[128], EA5s[128];
    __shared__ float Bs[64], EBs[64], EB5s[64];
    __shared__ float Ssum2[2][64];

    const int tid = threadIdx.x;

#pragma unroll
    for (int i = tid; i < 1024; i += 128) {
        const int cp = i >> 3, v = i & 7;
        *(float4*)&Hs[cp * 36 + v * 4] =
            *(const float4*)&g_h[(r * 128 + cp) * 128 + hh * 32 + v * 4];
    }
    {
        const int idx = (r * 128 + tid) * 4 + hh;
        As  [tid] = g_A  [idx];
        EAs [tid] = g_EA [idx];
        EA5s[tid] = g_EA5[idx];
    }
    if (tid < 64) {
        const int idx = (r * 128 + ch * 64 + tid) * 4 + hh;
        Bs  [tid] = g_B  [idx];
        EBs [tid] = g_EB [idx];
        EB5s[tid] = g_EB5[idx];
    }
    __syncthreads();

    const int d  = tid & 63;
    const int jh = tid >> 6;
    const float Bv   = Bs[d];
    const float EBv  = EBs[d];
    const float EB5v = EB5s[d];
    float srun = 0.f;

    const int dg = tid >> 3;
    const int qg = tid & 7;

    ull acc2[4][2];
#pragma unroll
    for (int a = 0; a < 4; a++) { acc2[a][0] = 0ull; acc2[a][1] = 0ull; }

    for (int cc = 0; cc < 4; cc++) {
#pragma unroll
        for (int jj = 0; jj < 16; jj++) {
            const int j  = jh * 16 + jj;
            const int jx = cc * 32 + j;
            const float xv = As[jx] + Bv;
            const float w = xv > 0.f ? EAs[jx] * EBv : EA5s[jx] * EB5v;
            ws[j * 68 + d] = w;
            srun += w;
        }
        __syncthreads();

#pragma unroll
        for (int j = 0; j < 32; j++) {
            const float4 wv = *(const float4*)&ws[j * 68 + dg * 4];
            const ulonglong2 hv = *(const ulonglong2*)&Hs[(cc * 32 + j) * 36 + qg * 4];
            ull ww;
            ww = pk2(wv.x, wv.x); fma2(acc2[0][0], ww, hv.x); fma2(acc2[0][1], ww, hv.y);
            ww = pk2(wv.y, wv.y); fma2(acc2[1][0], ww, hv.x); fma2(acc2[1][1], ww, hv.y);
            ww = pk2(wv.z, wv.z); fma2(acc2[2][0], ww, hv.x); fma2(acc2[2][1], ww, hv.y);
            ww = pk2(wv.w, wv.w); fma2(acc2[3][0], ww, hv.x); fma2(acc2[3][1], ww, hv.y);
        }
        __syncthreads();
    }

#pragma unroll
    for (int a = 0; a < 4; a++) {
        const int dst = ch * 64 + dg * 4 + a;
        const float2 lo = upk2(acc2[a][0]);
        const float2 hi = upk2(acc2[a][1]);
        *(float4*)&g_tmp[(r * 128 + dst) * 128 + hh * 32 + qg * 4] =
            make_float4(lo.x, lo.y, hi.x, hi.y);
    }

    Ssum2[jh][d] = srun;
    __syncthreads();
    if (tid < 64)
        g_srow[(r * 128 + ch * 64 + tid) * 4 + hh] = Ssum2[0][tid] + Ssum2[1][tid];
}

// ---------------------------------------------------------------------------
// K3: column aggregation + denominator finalize + normalize + bias + ELU.
// Block per column c: grid = 128, 384 threads, f32x2 inner loop.
// ---------------------------------------------------------------------------
__global__ void __launch_bounds__(384)
k_col_agg(const float* __restrict__ bias, float* __restrict__ out)
{
    const int c   = blockIdx.x;
    const int tid = threadIdx.x;

    __shared__ __align__(16) float Hs[48 * 136];
    __shared__ __align__(16) float ws[16 * 224];
    __shared__ float Acol[192], EAc[192], EA5c[192];
    __shared__ float Brc[192], EBrc[192], EB5rc[192];
    __shared__ float Srow[192], Rd[192];
    __shared__ float Sc2[2][192];
    __shared__ float bsh[128];

#pragma unroll
    for (int i = tid; i < 1536; i += 384) {
        const int t = i >> 5, v = i & 31;
        *(float4*)&Hs[t * 136 + v * 4] =
            *(const float4*)&g_h[(t * 128 + c) * 128 + v * 4];
    }
    if (tid < 192) {
        const int t = tid >> 2, h = tid & 3;
        const int idx = (t * 128 + c) * 4 + h;
        Acol [tid] = g_A   [idx];
        EAc  [tid] = g_EA  [idx];
        EA5c [tid] = g_EA5 [idx];
        Brc  [tid] = g_B   [idx];
        EBrc [tid] = g_EB  [idx];
        EB5rc[tid] = g_EB5 [idx];
        Srow [tid] = g_srow[idx];
    } else if (tid < 320) {
        bsh[tid - 192] = bias[tid - 192];
    }
    __syncthreads();

    const int k    = tid < 192 ? tid : tid - 192;
    const int half = tid < 192 ? 0 : 1;
    const int rr   = k >> 2;
    const int h    = k & 3;
    const float Bv   = Brc[k];
    const float EBv  = EBrc[k];
    const float EB5v = EB5rc[k];
    float scrun = 0.f;

    const int rg   = tid >> 5;
    const int head = (tid >> 3) & 3;
    const int qg   = tid & 7;

    ull acc2[4][2];
#pragma unroll
    for (int a = 0; a < 4; a++) { acc2[a][0] = 0ull; acc2[a][1] = 0ull; }

    for (int chunk = 0; chunk < 3; chunk++) {
        const int t0 = chunk * 16;
#pragma unroll
        for (int i = 0; i < 8; i++) {
            const int tl = half * 8 + i;
            const int t  = t0 + tl;
            const int sx = t * 4 + h;
            const float xv = Acol[sx] + Bv;
            float w = xv > 0.f ? EAc[sx] * EBv : EA5c[sx] * EB5v;
            if (t == rr) w = 0.f;
            ws[tl * 224 + h * 56 + rr] = w;
            scrun += w;
        }
        __syncthreads();

#pragma unroll
        for (int tl = 0; tl < 16; tl++) {
            const float4 wv = *(const float4*)&ws[tl * 224 + head * 56 + rg * 4];
            const ulonglong2 hv =
                *(const ulonglong2*)&Hs[(t0 + tl) * 136 + head * 32 + qg * 4];
            ull ww;
            ww = pk2(wv.x, wv.x); fma2(acc2[0][0], ww, hv.x); fma2(acc2[0][1], ww, hv.y);
            ww = pk2(wv.y, wv.y); fma2(acc2[1][0], ww, hv.x); fma2(acc2[1][1], ww, hv.y);
            ww = pk2(wv.z, wv.z); fma2(acc2[2][0], ww, hv.x); fma2(acc2[2][1], ww, hv.y);
            ww = pk2(wv.w, wv.w); fma2(acc2[3][0], ww, hv.x); fma2(acc2[3][1], ww, hv.y);
        }
        __syncthreads();
    }

    Sc2[half][k] = scrun;
    __syncthreads();
    if (tid < 192)
        Rd[tid] = 1.f / (Srow[tid] + Sc2[0][tid] + Sc2[1][tid]);
    __syncthreads();

    const int bb = head * 32 + qg * 4;
    const float4 bv = *(const float4*)&bsh[bb];
#pragma unroll
    for (int a = 0; a < 4; a++) {
        const int r = rg * 4 + a;
        const float rd = Rd[r * 4 + head];
        const int base = (r * 128 + c) * 128 + bb;
        const float4 tv = *(const float4*)&g_tmp[base];
        const float2 lo = upk2(acc2[a][0]);
        const float2 hi = upk2(acc2[a][1]);
        float v0 = (lo.x + tv.x) * rd + bv.x;
        float v1 = (lo.y + tv.y) * rd + bv.y;
        float v2 = (hi.x + tv.z) * rd + bv.z;
        float v3 = (hi.y + tv.w) * rd + bv.w;
        v0 = v0 > 0.f ? v0 : (__expf(v0) - 1.f);
        v1 = v1 > 0.f ? v1 : (__expf(v1) - 1.f);
        v2 = v2 > 0.f ? v2 : (__expf(v2) - 1.f);
        v3 = v3 > 0.f ? v3 : (__expf(v3) - 1.f);
        *(float4*)&out[base] = make_float4(v0, v1, v2, v3);
    }
}

// ---------------------------------------------------------------------------
static void run_layer(const float* x, const float* W, const float* asrc,
                      const float* adst, const float* bias, float* out)
{
    k_gemm_attn<<<NNODE / 16, 128>>>(x, W, asrc, adst);
    k_row_agg<<<T_TRIG * NHEADS * 2, 128>>>();
    k_col_agg<<<S_SPAN, 384>>>(bias, out);
}

extern "C" void kernel_launch(void* const* d_in, const int* in_sizes, int n_in,
                              void* d_out, int out_size)
{
    const float* x0  = (const float*)d_in[0];
    const float* W1  = (const float*)d_in[1];
    const float* as1 = (const float*)d_in[2];
    const float* ad1 = (const float*)d_in[3];
    const float* b1  = (const float*)d_in[4];
    const float* W2  = (const float*)d_in[5];
    const float* as2 = (const float*)d_in[6];
    const float* ad2 = (const float*)d_in[7];
    const float* b2  = (const float*)d_in[8];

    float* x1 = nullptr;
    cudaGetSymbolAddress((void**)&x1, g_x1);

    run_layer(x0, W1, as1, ad1, b1, x1);
    run_layer(x1, W2, as2, ad2, b2, (float*)d_out);
}